// round 11
// baseline (speedup 1.0000x reference)
#include <cuda_runtime.h>
#include <cuda_fp16.h>
#include <cstdint>

#define NTH     128
#define PT      128
#define NPT     78
#define NTILES  (128 * NPT)
#define PLEN    9984
#define LL      10000
#define NK      128

// smem layout (bytes)
#define XS_OFF  0                 // 2 x 160 float4 (144 used) = 5120B
#define W_OFF   5120              // 64KB: W'[k=128][s=256] fp16, blocked SW128
#define P0_OFF  70656             // 2 x 6912B: P[144 rows][16 cc] fp16, 48B row stride
#define PSZ     6912
#define SMEM_TOTAL 84480

static __device__ __forceinline__ uint32_t s2u(const void* p) {
    uint32_t a;
    asm("{ .reg .u64 t; cvta.to.shared.u64 t, %1; cvt.u32.u64 %0, t; }" : "=r"(a) : "l"(p));
    return a;
}

// Blocked SW128 atom layout for W [128 rows x 256 halves]; atom = 8 rows x 128B, rstride 16.
static __device__ __forceinline__ uint32_t wa(int row, int s) {
    uint32_t byte = (uint32_t)((((row >> 3) + ((s >> 6) << 4)) << 10) + ((row & 7) << 7) + ((s & 63) << 1));
    return byte ^ ((byte >> 3) & 0x70);
}
// Unswizzled byte offset (incremental addressing adds here, then XORs the mask)
static __device__ __forceinline__ uint32_t wa_u(int row, int s) {
    return (uint32_t)((((row >> 3) + ((s >> 6) << 4)) << 10) + ((row & 7) << 7) + ((s & 63) << 1));
}

static __device__ __forceinline__ uint32_t f2h2(float a, float b) {
    __half2 h = __floats2half2_rn(a, b);
    return *reinterpret_cast<uint32_t*>(&h);
}

static __device__ __forceinline__ void ldsm4(uint32_t (&r)[4], uint32_t addr) {
    asm volatile("ldmatrix.sync.aligned.m8n8.x4.shared.b16 {%0,%1,%2,%3}, [%4];"
        : "=r"(r[0]), "=r"(r[1]), "=r"(r[2]), "=r"(r[3]) : "r"(addr));
}

static __device__ __forceinline__ void sts128(uint32_t addr, uint4 v) {
    asm volatile("st.shared.v4.b32 [%0], {%1,%2,%3,%4};"
        :: "r"(addr), "r"(v.x), "r"(v.y), "r"(v.z), "r"(v.w));
}

static __device__ __forceinline__ void mma16816(float (&d)[4], const uint32_t (&a)[4],
                                                uint32_t b0, uint32_t b1) {
    asm volatile("mma.sync.aligned.m16n8k16.row.col.f32.f16.f16.f32 "
        "{%0,%1,%2,%3}, {%4,%5,%6,%7}, {%8,%9}, {%0,%1,%2,%3};"
        : "+f"(d[0]), "+f"(d[1]), "+f"(d[2]), "+f"(d[3])
        : "r"(a[0]), "r"(a[1]), "r"(a[2]), "r"(a[3]), "r"(b0), "r"(b1));
}

// P row t: P[t][c1*4+c2] = x[t][c1] * x[t+1][c2]; 16 halves = 32B at t*48 (48B stride).
static __device__ __forceinline__ void build_p(uint32_t pbase, const float4* xs, int t) {
    const float4 a = xs[t], c = xs[t + 1];
    uint4 lo, hi;
    lo.x = f2h2(a.x * c.x, a.x * c.y); lo.y = f2h2(a.x * c.z, a.x * c.w);
    lo.z = f2h2(a.y * c.x, a.y * c.y); lo.w = f2h2(a.y * c.z, a.y * c.w);
    hi.x = f2h2(a.z * c.x, a.z * c.y); hi.y = f2h2(a.z * c.z, a.z * c.w);
    hi.z = f2h2(a.w * c.x, a.w * c.y); hi.w = f2h2(a.w * c.z, a.w * c.w);
    sts128(pbase + t * 48, lo);
    sts128(pbase + t * 48 + 16, hi);
}

static __device__ __forceinline__ const float4* xwin(const float* x, int tile) {
    const int b = tile / NPT, p0 = (tile - b * NPT) * PT;
    return (const float4*)(x + ((size_t)b * LL + p0) * 4);
}

__global__ void __launch_bounds__(NTH, 2)
markonv_kernel(const float* __restrict__ x, const float* __restrict__ ker,
               float* __restrict__ out) {
    extern __shared__ char smem[];
    uint32_t sb = s2u(smem);
    const int tid = threadIdx.x;
    const int lane = tid & 31;
    const int wid = tid >> 5;
    const int wm = wid & 1;   // warp M (k): 2 x 64 rows
    const int wn = wid >> 1;  // warp N (p): 2 x 64 cols
    const int G = gridDim.x;

    // ---- stage W once per CTA: W'[k][s] = ker[s*128 + k] ----
    for (int idx = tid; idx < 128 * 128; idx += NTH) {
        int k = idx & 127, s = (idx >> 7) << 1;
        *(uint32_t*)(smem + W_OFF + wa(k, s)) =
            f2h2(ker[s * 128 + k], ker[s * 128 + 128 + k]);
    }

    // A (W) lane addressing: unswizzled base + per-thread XOR mask (bits 4-6).
    const int a_row = wm * 64 + (lane & 15);
    const uint32_t wbyteU = wa_u(a_row, (lane >> 4) << 3);
    const uint32_t wmask  = (uint32_t)((a_row & 7) << 4);
    // B (P) lane addressing: linear; per-kstep +48, rows +16 -> +768.
    const uint32_t pblane = (uint32_t)((wn * 64 + (lane & 7) + ((lane >> 4) << 3)) * 48
                                       + (((lane >> 3) & 1) << 4));

    int tile = blockIdx.x;
    float4 xr = make_float4(0.f, 0.f, 0.f, 0.f), xrb = xr;

    // ---- prologue: stage xs[0], build P[0], prefetch x(tile+G) ----
    {
        const float4* w0 = xwin(x, tile);
        xr = w0[tid];
        if (tid < 16) xrb = w0[128 + tid];
        float4* xs0 = (float4*)(smem + XS_OFF);
        xs0[tid] = xr;
        if (tid < 16) xs0[128 + tid] = xrb;
        __syncthreads();
        build_p(sb + P0_OFF, xs0, tid);
        if (tid < 16) build_p(sb + P0_OFF, xs0, 128 + tid);
        if (tile + G < NTILES) {
            const float4* w1 = xwin(x, tile + G);
            xr = w1[tid];
            if (tid < 16) xrb = w1[128 + tid];
        }
    }

    int n = 0;
    for (; tile < NTILES; tile += G, n++) {
        const int cb = n & 1, nb = cb ^ 1;

        // publish x window for tile+G; barrier publishes P[cb] and xs[nb]
        float4* xsn = (float4*)(smem + XS_OFF) + nb * 160;
        xsn[tid] = xr;
        if (tid < 16) xsn[128 + tid] = xrb;
        __syncthreads();

        const int b = tile / NPT;
        const int p0 = (tile - b * NPT) * PT;

        // prefetch x(tile+2G)
        if (tile + 2 * G < NTILES) {
            const float4* w2 = xwin(x, tile + 2 * G);
            xr = w2[tid];
            if (tid < 16) xrb = w2[128 + tid];
        }

        // build P[nb] (tiny: 144 rows)
        {
            const uint32_t pn = sb + P0_OFF + nb * PSZ;
            build_p(pn, xsn, tid);
            if (tid < 16) build_p(pn, xsn, 128 + tid);
        }

        // ---- GEMM: D[128k x 128p] = W * V^T, V[p][16ks+cc] = P[p+ks][cc] ----
        const uint32_t pcur = sb + P0_OFF + cb * PSZ + pblane;
        const uint32_t wsb  = sb + W_OFF;

        float acc[4][8][4];
        #pragma unroll
        for (int mf = 0; mf < 4; mf++)
            #pragma unroll
            for (int nf = 0; nf < 8; nf++)
                #pragma unroll
                for (int e = 0; e < 4; e++) acc[mf][nf][e] = 0.f;

        #pragma unroll
        for (int ks = 0; ks < 16; ks++) {
            uint32_t af[4][4], bf[4][4];
            const uint32_t d = (uint32_t)((ks >> 2) * 16384 + (ks & 3) * 32);
            const uint32_t ab = wsb + ((wbyteU + d) ^ wmask);
            const uint32_t bb = pcur + (uint32_t)(ks * 48);
            ldsm4(af[0], ab);
            ldsm4(af[1], ab + 2048);
            ldsm4(af[2], ab + 4096);
            ldsm4(af[3], ab + 6144);
            ldsm4(bf[0], bb);
            ldsm4(bf[1], bb + 768);
            ldsm4(bf[2], bb + 1536);
            ldsm4(bf[3], bb + 2304);
            #pragma unroll
            for (int j = 0; j < 4; j++)
                #pragma unroll
                for (int mf = 0; mf < 4; mf++) {
                    mma16816(acc[mf][2 * j],     af[mf], bf[j][0], bf[j][1]);
                    mma16816(acc[mf][2 * j + 1], af[mf], bf[j][2], bf[j][3]);
                }
        }

        // ---- epilogue: direct STG.64 (rows = k, cols = consecutive p) ----
        {
            const size_t obase = ((size_t)b * NK + wm * 64) * PLEN + p0 + wn * 64;
            const int krow = lane >> 2;
            const int pcol = (lane & 3) * 2;
            #pragma unroll
            for (int mf = 0; mf < 4; mf++) {
                #pragma unroll
                for (int nf = 0; nf < 8; nf++) {
                    size_t o = obase + (size_t)(mf * 16 + krow) * PLEN + nf * 8 + pcol;
                    *(float2*)(out + o)            = make_float2(acc[mf][nf][0], acc[mf][nf][1]);
                    *(float2*)(out + o + 8 * PLEN) = make_float2(acc[mf][nf][2], acc[mf][nf][3]);
                }
            }
        }
    }
}

extern "C" void kernel_launch(void* const* d_in, const int* in_sizes, int n_in,
                              void* d_out, int out_size) {
    static int nsm = 0;
    if (nsm == 0) {
        int dev = 0;
        cudaGetDevice(&dev);
        if (cudaDeviceGetAttribute(&nsm, cudaDevAttrMultiProcessorCount, dev) != cudaSuccess || nsm <= 0)
            nsm = 148;
        cudaFuncSetAttribute(markonv_kernel, cudaFuncAttributeMaxDynamicSharedMemorySize, SMEM_TOTAL);
    }
    markonv_kernel<<<2 * nsm, NTH, SMEM_TOTAL>>>(
        (const float*)d_in[0], (const float*)d_in[1], (float*)d_out);
}